// round 3
// baseline (speedup 1.0000x reference)
#include <cuda_runtime.h>
#include <cstdint>
#include <math.h>

#define BSZ 64
#define TSZ 512
#define ESZ 256
#define USZ 512
#define GSZ 2048
#define NBLK 128

// Scratch (static device allocations only)
__device__ float g_xz[(size_t)2 * TSZ * USZ * 4 * BSZ];   // [dir][t][u][gate][b]
__device__ float g_h[2][2][USZ * BSZ];                    // [dir][parity][u][b]
__device__ unsigned g_bar_cnt;
__device__ unsigned g_pad_[31];
__device__ unsigned g_bar_gen;

// ---- packed f32x2 helpers (Blackwell FFMA2 path) ----
__device__ __forceinline__ void ffma2(unsigned long long& d,
                                      unsigned long long a,
                                      unsigned long long b) {
    asm("fma.rn.f32x2 %0, %1, %2, %0;" : "+l"(d) : "l"(a), "l"(b));
}
__device__ __forceinline__ void addf2(unsigned long long& d, unsigned long long a) {
    asm("add.rn.f32x2 %0, %0, %1;" : "+l"(d) : "l"(a));
}
__device__ __forceinline__ unsigned long long splat2(float x) {
    unsigned long long r;
    unsigned u = __float_as_uint(x);
    asm("mov.b64 %0, {%1, %1};" : "=l"(r) : "r"(u));
    return r;
}
__device__ __forceinline__ unsigned long long pack2(float lo, float hi) {
    unsigned long long r;
    asm("mov.b64 %0, {%1, %2};" : "=l"(r) : "r"(__float_as_uint(lo)), "r"(__float_as_uint(hi)));
    return r;
}
__device__ __forceinline__ void unpack2(unsigned long long v, float& lo, float& hi) {
    unsigned a, b;
    asm("mov.b64 {%0, %1}, %2;" : "=r"(a), "=r"(b) : "l"(v));
    lo = __uint_as_float(a); hi = __uint_as_float(b);
}

__device__ __forceinline__ void grid_barrier() {
    __syncthreads();
    if (threadIdx.x == 0) {
        __threadfence();
        unsigned gen = atomicAdd(&g_bar_gen, 0u);
        unsigned a = atomicAdd(&g_bar_cnt, 1u);
        if (a == NBLK - 1) {
            atomicExch(&g_bar_cnt, 0u);
            __threadfence();
            atomicAdd(&g_bar_gen, 1u);
        } else {
            while (atomicAdd(&g_bar_gen, 0u) == gen) { __nanosleep(32); }
        }
        __threadfence();
    }
    __syncthreads();
}

// ---------------------------------------------------------------------------
// Kernel 1: xz[dir][t][u][g][b] = (emb[idx[b][t]] @ W_dir + b_dir)
// 128x64 tile, FFMA2 inner loop.
// ---------------------------------------------------------------------------
__global__ void __launch_bounds__(256) xz_gemm_kernel(
    const int* __restrict__ idx, const float* __restrict__ emb,
    const float* __restrict__ Wf, const float* __restrict__ bf,
    const float* __restrict__ Wb, const float* __restrict__ bb)
{
    const int dir = blockIdx.z;
    const float* __restrict__ W    = dir ? Wb : Wf;
    const float* __restrict__ bias = dir ? bb : bf;
    float* __restrict__ xz = g_xz + (size_t)dir * TSZ * USZ * 4 * BSZ;

    __shared__ float As[16 * 128];
    __shared__ float Bs[16 * 64];
    __shared__ int rowv[128];

    const int tid   = threadIdx.x;
    const int rbase = blockIdx.y * 128;
    const int nbase = blockIdx.x * 64;

    if (tid < 128) {
        int r = rbase + tid;
        int t = r >> 6, b = r & 63;
        rowv[tid] = idx[b * TSZ + t];
    }
    __syncthreads();

    const int ty = tid >> 4, tx = tid & 15;
    unsigned long long acc2[8][2];
#pragma unroll
    for (int i = 0; i < 8; i++) { acc2[i][0] = 0ull; acc2[i][1] = 0ull; }

    const int lm  = tid >> 1;
    const int lkq = (tid & 1) * 8;
    const int lrow = rowv[lm];
    const int lk  = tid >> 4;
    const int ln4 = (tid & 15) * 4;

    for (int kt = 0; kt < ESZ; kt += 16) {
        float4 a0 = *(const float4*)&emb[(size_t)lrow * ESZ + kt + lkq];
        float4 a1 = *(const float4*)&emb[(size_t)lrow * ESZ + kt + lkq + 4];
        float4 bv = *(const float4*)&W[(size_t)(kt + lk) * GSZ + nbase + ln4];

        As[(lkq + 0) * 128 + lm] = a0.x;
        As[(lkq + 1) * 128 + lm] = a0.y;
        As[(lkq + 2) * 128 + lm] = a0.z;
        As[(lkq + 3) * 128 + lm] = a0.w;
        As[(lkq + 4) * 128 + lm] = a1.x;
        As[(lkq + 5) * 128 + lm] = a1.y;
        As[(lkq + 6) * 128 + lm] = a1.z;
        As[(lkq + 7) * 128 + lm] = a1.w;
        *(float4*)&Bs[lk * 64 + ln4] = bv;
        __syncthreads();

#pragma unroll
        for (int k = 0; k < 16; ++k) {
            ulonglong2 rb = *(const ulonglong2*)&Bs[k * 64 + tx * 4];
            float4 ra0 = *(const float4*)&As[k * 128 + ty * 8];
            float4 ra1 = *(const float4*)&As[k * 128 + ty * 8 + 4];
            unsigned long long s;
            s = splat2(ra0.x); ffma2(acc2[0][0], s, rb.x); ffma2(acc2[0][1], s, rb.y);
            s = splat2(ra0.y); ffma2(acc2[1][0], s, rb.x); ffma2(acc2[1][1], s, rb.y);
            s = splat2(ra0.z); ffma2(acc2[2][0], s, rb.x); ffma2(acc2[2][1], s, rb.y);
            s = splat2(ra0.w); ffma2(acc2[3][0], s, rb.x); ffma2(acc2[3][1], s, rb.y);
            s = splat2(ra1.x); ffma2(acc2[4][0], s, rb.x); ffma2(acc2[4][1], s, rb.y);
            s = splat2(ra1.y); ffma2(acc2[5][0], s, rb.x); ffma2(acc2[5][1], s, rb.y);
            s = splat2(ra1.z); ffma2(acc2[6][0], s, rb.x); ffma2(acc2[6][1], s, rb.y);
            s = splat2(ra1.w); ffma2(acc2[7][0], s, rb.x); ffma2(acc2[7][1], s, rb.y);
        }
        __syncthreads();
    }

    // epilogue: rows r0..r0+7 share one t; store [t][u][g][b]
    float accf[8][4];
#pragma unroll
    for (int i = 0; i < 8; ++i) {
        unpack2(acc2[i][0], accf[i][0], accf[i][1]);
        unpack2(acc2[i][1], accf[i][2], accf[i][3]);
    }
    const int r0 = rbase + ty * 8;
    const int t  = r0 >> 6;
    const int b0 = r0 & 63;
#pragma unroll
    for (int j = 0; j < 4; ++j) {
        int n = nbase + tx * 4 + j;
        int u = n & 511, g = n >> 9;
        float bv = bias[n];
        float* p = &xz[(((size_t)t * USZ + u) * 4 + g) * BSZ + b0];
        float4 v0 = { accf[0][j] + bv, accf[1][j] + bv, accf[2][j] + bv, accf[3][j] + bv };
        float4 v1 = { accf[4][j] + bv, accf[5][j] + bv, accf[6][j] + bv, accf[7][j] + bv };
        *(float4*)p       = v0;
        *(float4*)(p + 4) = v1;
    }
}

// ---------------------------------------------------------------------------
// Kernel 2: persistent bidirectional LSTM scan, FFMA2 inner loop.
// 128 blocks x 256 threads. Block = (dir, 8 units). Threads split k into two
// halves; partial accs reduced through smem. U slice resident in smem for all
// 512 steps; h double-buffered in global, staged to smem per step.
// ---------------------------------------------------------------------------
__global__ void __launch_bounds__(256) lstm_scan_kernel(
    const int* __restrict__ idx,
    const float* __restrict__ Uf, const float* __restrict__ Ub,
    float* __restrict__ out)
{
    extern __shared__ float smem[];
    float* Us = smem;                                   // [k][32] (ul*4+g) 64KB
    float* hs = smem + 16384;                           // [k][64] 128KB
    unsigned long long* red = (unsigned long long*)(smem + 16384 + 32768); // 1024 u64, 8KB
    unsigned long long* msk = (unsigned long long*)(red + 1024);           // 512 u64, 4KB

    const int tid    = threadIdx.x;
    const int khalf  = tid >> 7;       // 0 or 1
    const int tid2   = tid & 127;
    const int bg     = tid2 & 15;
    const int ul     = tid2 >> 4;
    const int bid    = blockIdx.x;
    const int dir    = bid >> 6;
    const int ublock = bid & 63;
    const int u      = ublock * 8 + ul;
    const float* __restrict__ Um = dir ? Ub : Uf;
    const float* __restrict__ xz = g_xz + (size_t)dir * TSZ * USZ * 4 * BSZ;

    // one-time: stage U slice (gate-interleaved) into smem
    for (int i = tid; i < 16384; i += 256) {
        int k = i >> 5;
        int r = i & 31;
        int uu = ublock * 8 + (r >> 2);
        int g  = r & 3;
        Us[i] = Um[(size_t)k * GSZ + g * USZ + uu];
    }
    // one-time: masks
    for (int tt = tid * 2; tt < tid * 2 + 2; ++tt) {
        unsigned long long m = 0ull;
        for (int b = 0; b < 64; ++b)
            if (idx[b * TSZ + tt] != 0) m |= (1ull << b);
        msk[tt] = m;
    }
    // init h parity-0 (set A only: covers all (u, bg))
    if (khalf == 0) {
        float4 z4 = { 0.f, 0.f, 0.f, 0.f };
        *(float4*)&g_h[dir][0][u * BSZ + bg * 4] = z4;
    }
    grid_barrier();

    float c_st[4] = { 0.f, 0.f, 0.f, 0.f };
    float h_st[4] = { 0.f, 0.f, 0.f, 0.f };
    const int k0 = khalf * 256;

    for (int s = 0; s < TSZ; ++s) {
        const int t   = dir ? (TSZ - 1 - s) : s;
        const int cur = s & 1, nxt = cur ^ 1;

        // init accumulators: set A folds in xz, set B starts at zero
        unsigned long long a2[2][4];
        if (khalf == 0) {
            const float* xzt = xz + (((size_t)t * USZ + u) * 4) * BSZ;
#pragma unroll
            for (int g = 0; g < 4; ++g) {
                float4 v = *(const float4*)&xzt[g * BSZ + bg * 4];
                a2[0][g] = pack2(v.x, v.y);
                a2[1][g] = pack2(v.z, v.w);
            }
        } else {
#pragma unroll
            for (int g = 0; g < 4; ++g) { a2[0][g] = 0ull; a2[1][g] = 0ull; }
        }

        // stage h [512][64] into smem
        {
            const float4* src = (const float4*)&g_h[dir][cur][0];
            float4* dst = (float4*)hs;
#pragma unroll
            for (int i = 0; i < 32; ++i)
                dst[tid + i * 256] = src[tid + i * 256];
        }
        __syncthreads();

        // FFMA2 inner loop over this thread's k-half
        {
            const float* hsk = hs + k0 * 64 + bg * 4;
            const float* usk = Us + k0 * 32 + ul * 4;
#pragma unroll 4
            for (int k = 0; k < 256; ++k) {
                ulonglong2 hv = *(const ulonglong2*)hsk; hsk += 64;
                float4 uv = *(const float4*)usk;         usk += 32;
                unsigned long long s0 = splat2(uv.x);
                unsigned long long s1 = splat2(uv.y);
                unsigned long long s2 = splat2(uv.z);
                unsigned long long s3 = splat2(uv.w);
                ffma2(a2[0][0], hv.x, s0); ffma2(a2[0][1], hv.x, s1);
                ffma2(a2[0][2], hv.x, s2); ffma2(a2[0][3], hv.x, s3);
                ffma2(a2[1][0], hv.y, s0); ffma2(a2[1][1], hv.y, s1);
                ffma2(a2[1][2], hv.y, s2); ffma2(a2[1][3], hv.y, s3);
            }
        }

        // k-half reduction through smem
        if (khalf == 1) {
            unsigned long long* r = red + tid2 * 8;
#pragma unroll
            for (int g = 0; g < 4; ++g) { r[g] = a2[0][g]; r[4 + g] = a2[1][g]; }
        }
        __syncthreads();

        if (khalf == 0) {
            const unsigned long long* r = red + tid2 * 8;
#pragma unroll
            for (int g = 0; g < 4; ++g) { addf2(a2[0][g], r[g]); addf2(a2[1][g], r[4 + g]); }

            float z[4][4];
#pragma unroll
            for (int g = 0; g < 4; ++g) {
                unpack2(a2[0][g], z[0][g], z[1][g]);
                unpack2(a2[1][g], z[2][g], z[3][g]);
            }

            const unsigned long long mw = msk[t];
#pragma unroll
            for (int bi = 0; bi < 4; ++bi) {
                int b = bg * 4 + bi;
                float ig = 1.f / (1.f + expf(-z[bi][0]));
                float fg = 1.f / (1.f + expf(-z[bi][1]));
                float gg = tanhf(z[bi][2]);
                float og = 1.f / (1.f + expf(-z[bi][3]));
                float cn = fg * c_st[bi] + ig * gg;
                float hn = og * tanhf(cn);
                if ((mw >> b) & 1ull) { c_st[bi] = cn; h_st[bi] = hn; }
                out[((size_t)b * TSZ + t) * 1024 + dir * USZ + u] = h_st[bi];
            }
            float4 hv = { h_st[0], h_st[1], h_st[2], h_st[3] };
            *(float4*)&g_h[dir][nxt][u * BSZ + bg * 4] = hv;
        }
        grid_barrier();
    }

    // final states (set A owns state)
    if (khalf == 0) {
        const size_t H0 = (size_t)BSZ * TSZ * 1024;
        const size_t C0 = H0 + (size_t)BSZ * 1024;
#pragma unroll
        for (int bi = 0; bi < 4; ++bi) {
            int b = bg * 4 + bi;
            out[H0 + (size_t)b * 1024 + dir * USZ + u] = h_st[bi];
            out[C0 + (size_t)b * 1024 + dir * USZ + u] = c_st[bi];
        }
    }
}

// ---------------------------------------------------------------------------
extern "C" void kernel_launch(void* const* d_in, const int* in_sizes, int n_in,
                              void* d_out, int out_size)
{
    const int*   idx = (const int*)  d_in[0];
    const float* emb = (const float*)d_in[1];
    const float* Wf  = (const float*)d_in[2];
    const float* Uf  = (const float*)d_in[3];
    const float* bf  = (const float*)d_in[4];
    const float* Wb  = (const float*)d_in[5];
    const float* Ub  = (const float*)d_in[6];
    const float* bb  = (const float*)d_in[7];
    float* out = (float*)d_out;

    dim3 ggrid(GSZ / 64, (BSZ * TSZ) / 128, 2);
    xz_gemm_kernel<<<ggrid, 256>>>(idx, emb, Wf, bf, Wb, bb);

    const int smem_bytes = (16384 + 32768) * 4 + 1024 * 8 + 512 * 8;  // 208896
    cudaFuncSetAttribute(lstm_scan_kernel,
                         cudaFuncAttributeMaxDynamicSharedMemorySize, smem_bytes);
    lstm_scan_kernel<<<NBLK, 256, smem_bytes>>>(idx, Uf, Ub, out);
}

// round 8
// speedup vs baseline: 1.6296x; 1.6296x over previous
#include <cuda_runtime.h>
#include <cstdint>
#include <math.h>

#define BSZ 64
#define TSZ 512
#define ESZ 256
#define USZ 512
#define GSZ 2048
#define NBLK 128
#define NBLK_DIR 64

// Scratch (static device allocations only)
__device__ float g_xz[(size_t)2 * TSZ * 4 * BSZ * USZ];   // [dir][t][g][b][u]
__device__ float g_h[2][2][USZ * BSZ];                    // [dir][parity][u][b]
__device__ unsigned g_bar_cnt[64];                        // [dir*32]
__device__ unsigned g_bar_gen[64];                        // [dir*32]

// ---- packed f32x2 helpers ----
__device__ __forceinline__ void ffma2(unsigned long long& d,
                                      unsigned long long a,
                                      unsigned long long b) {
    asm("fma.rn.f32x2 %0, %1, %2, %0;" : "+l"(d) : "l"(a), "l"(b));
}
__device__ __forceinline__ void addf2(unsigned long long& d, unsigned long long a) {
    asm("add.rn.f32x2 %0, %0, %1;" : "+l"(d) : "l"(a));
}
__device__ __forceinline__ unsigned long long splat2(float x) {
    unsigned long long r;
    unsigned u = __float_as_uint(x);
    asm("mov.b64 %0, {%1, %1};" : "=l"(r) : "r"(u));
    return r;
}
__device__ __forceinline__ unsigned long long pack2(float lo, float hi) {
    unsigned long long r;
    asm("mov.b64 %0, {%1, %2};" : "=l"(r) : "r"(__float_as_uint(lo)), "r"(__float_as_uint(hi)));
    return r;
}
__device__ __forceinline__ void unpack2(unsigned long long v, float& lo, float& hi) {
    unsigned a, b;
    asm("mov.b64 {%0, %1}, %2;" : "=r"(a), "=r"(b) : "l"(v));
    lo = __uint_as_float(a); hi = __uint_as_float(b);
}

__device__ __forceinline__ float sigf(float x) {
    return __fdividef(1.f, 1.f + __expf(-x));
}
__device__ __forceinline__ float tanhf_(float x) {
    return __fdividef(2.f, 1.f + __expf(-2.f * x)) - 1.f;
}

__device__ __forceinline__ void grid_barrier(int dir) {
    __syncthreads();
    if (threadIdx.x == 0) {
        __threadfence();
        unsigned* cnt = &g_bar_cnt[dir * 32];
        unsigned* gen = &g_bar_gen[dir * 32];
        unsigned g0 = atomicAdd(gen, 0u);
        unsigned a = atomicAdd(cnt, 1u);
        if (a == NBLK_DIR - 1) {
            atomicExch(cnt, 0u);
            __threadfence();
            atomicAdd(gen, 1u);
        } else {
            while (atomicAdd(gen, 0u) == g0) { __nanosleep(32); }
        }
        __threadfence();
    }
    __syncthreads();
}

// ---------------------------------------------------------------------------
// Kernel 1: xz[dir][t][g][b][u] = (emb[idx[b][t]] @ W_dir + b_dir)
// 128x128 tile, 256 threads, FFMA2 with row-pair lanes.
// ---------------------------------------------------------------------------
__global__ void __launch_bounds__(256) xz_gemm_kernel(
    const int* __restrict__ idx, const float* __restrict__ emb,
    const float* __restrict__ Wf, const float* __restrict__ bf,
    const float* __restrict__ Wb, const float* __restrict__ bb)
{
    const int dir = blockIdx.z;
    const float* __restrict__ W    = dir ? Wb : Wf;
    const float* __restrict__ bias = dir ? bb : bf;
    float* __restrict__ xz = g_xz + (size_t)dir * TSZ * 4 * BSZ * USZ;

    __shared__ float As[16 * 128];
    __shared__ float Bs[16 * 128];
    __shared__ int rowv[128];

    const int tid   = threadIdx.x;
    const int rbase = blockIdx.y * 128;   // rows r = t*64 + b
    const int nbase = blockIdx.x * 128;   // cols n = g*512 + u

    if (tid < 128) {
        int r = rbase + tid;
        int t = r >> 6, b = r & 63;
        rowv[tid] = idx[b * TSZ + t];
    }
    __syncthreads();

    const int ty = tid >> 4, tx = tid & 15;
    unsigned long long acc2[4][8];   // lanes = row pairs (ty*8+2rp, +1); cols tx+16j
#pragma unroll
    for (int i = 0; i < 4; i++)
#pragma unroll
        for (int j = 0; j < 8; j++) acc2[i][j] = 0ull;

    const int lm  = tid >> 1;
    const int lkq = (tid & 1) * 8;
    const int lrow = rowv[lm];
    const int lk  = tid >> 4;
    const int lc  = (tid & 15) * 8;

    for (int kt = 0; kt < ESZ; kt += 16) {
        float4 a0 = *(const float4*)&emb[(size_t)lrow * ESZ + kt + lkq];
        float4 a1 = *(const float4*)&emb[(size_t)lrow * ESZ + kt + lkq + 4];
        float4 b0 = *(const float4*)&W[(size_t)(kt + lk) * GSZ + nbase + lc];
        float4 b1 = *(const float4*)&W[(size_t)(kt + lk) * GSZ + nbase + lc + 4];

        As[(lkq + 0) * 128 + lm] = a0.x;
        As[(lkq + 1) * 128 + lm] = a0.y;
        As[(lkq + 2) * 128 + lm] = a0.z;
        As[(lkq + 3) * 128 + lm] = a0.w;
        As[(lkq + 4) * 128 + lm] = a1.x;
        As[(lkq + 5) * 128 + lm] = a1.y;
        As[(lkq + 6) * 128 + lm] = a1.z;
        As[(lkq + 7) * 128 + lm] = a1.w;
        *(float4*)&Bs[lk * 128 + lc]     = b0;
        *(float4*)&Bs[lk * 128 + lc + 4] = b1;
        __syncthreads();

#pragma unroll
        for (int k = 0; k < 16; ++k) {
            ulonglong2 ra01 = *(const ulonglong2*)&As[k * 128 + ty * 8];
            ulonglong2 ra23 = *(const ulonglong2*)&As[k * 128 + ty * 8 + 4];
            const float* bs = &Bs[k * 128 + tx];
            float bj[8];
#pragma unroll
            for (int j = 0; j < 8; ++j) bj[j] = bs[16 * j];
#pragma unroll
            for (int j = 0; j < 8; ++j) {
                unsigned long long s = splat2(bj[j]);
                ffma2(acc2[0][j], ra01.x, s);
                ffma2(acc2[1][j], ra01.y, s);
                ffma2(acc2[2][j], ra23.x, s);
                ffma2(acc2[3][j], ra23.y, s);
            }
        }
        __syncthreads();
    }

    // epilogue: write [t][g][b][u]
    const int r0 = rbase + ty * 8;
    const int t  = r0 >> 6;
    const int b0 = r0 & 63;
#pragma unroll
    for (int j = 0; j < 8; ++j) {
        int n = nbase + tx + 16 * j;
        int g = n >> 9, u = n & 511;
        float bv = bias[n];
        float* base = &xz[(((size_t)t * 4 + g) * BSZ) * USZ + u];
#pragma unroll
        for (int rp = 0; rp < 4; ++rp) {
            float lo, hi;
            unpack2(acc2[rp][j], lo, hi);
            base[(size_t)(b0 + 2 * rp) * USZ]     = lo + bv;
            base[(size_t)(b0 + 2 * rp + 1) * USZ] = hi + bv;
        }
    }
}

// ---------------------------------------------------------------------------
// Kernel 2: persistent bidirectional LSTM scan.
// 128 blocks x 256 threads. Block = (dir, 8 units). 4-way k split:
// tid = kq*64 + r;  r = up*16 + bg;  thread covers units (u0,u0+1) packed in
// f32x2 lanes x 4 gates x 4 batches. U pre-packed as u64 pairs in smem.
// ---------------------------------------------------------------------------
__global__ void __launch_bounds__(256) lstm_scan_kernel(
    const int* __restrict__ idx,
    const float* __restrict__ Uf, const float* __restrict__ Ub,
    float* __restrict__ out)
{
    extern __shared__ float smem[];
    unsigned long long* Us2 = (unsigned long long*)smem;        // [k][up][g] u64 pairs, 64KB
    float* hs = smem + 16384;                                   // [k][b], 128KB
    unsigned long long* red = (unsigned long long*)(smem + 16384 + 32768); // [3][64][16], 24KB
    unsigned long long* msk = red + 3 * 64 * 16;                // [512], 4KB

    const int tid    = threadIdx.x;
    const int kq     = tid >> 6;        // 0..3
    const int r      = tid & 63;
    const int up     = r >> 4;          // 0..3
    const int bg     = r & 15;          // 4 batches each
    const int bid    = blockIdx.x;
    const int dir    = bid >> 6;
    const int ublock = bid & 63;
    const int u0     = ublock * 8 + up * 2;   // lanes: (u0, u0+1)
    const float* __restrict__ Um = dir ? Ub : Uf;
    const float* __restrict__ xz = g_xz + (size_t)dir * TSZ * 4 * BSZ * USZ;

    // one-time: U pairs into smem: Us2[(k*4+up)*4+g] = (U[k][g*512+u0], U[k][g*512+u0+1])
    for (int i = tid; i < 512 * 16; i += 256) {
        int k  = i >> 4;
        int pu = (i >> 2) & 3;
        int g  = i & 3;
        float2 v = *(const float2*)&Um[(size_t)k * GSZ + g * USZ + ublock * 8 + pu * 2];
        Us2[i] = pack2(v.x, v.y);
    }
    // one-time: masks
    for (int tt = tid * 2; tt < tid * 2 + 2; ++tt) {
        unsigned long long m = 0ull;
        for (int b = 0; b < 64; ++b)
            if (idx[b * TSZ + tt] != 0) m |= (1ull << b);
        msk[tt] = m;
    }
    // init h parity-0 (kq0 threads cover all (u, b))
    if (kq == 0) {
        float4 z4 = { 0.f, 0.f, 0.f, 0.f };
        *(float4*)&g_h[dir][0][u0 * BSZ + bg * 4]       = z4;
        *(float4*)&g_h[dir][0][(u0 + 1) * BSZ + bg * 4] = z4;
    }
    grid_barrier(dir);

    float c_st[2][4] = {{0.f,0.f,0.f,0.f},{0.f,0.f,0.f,0.f}};
    float h_st[2][4] = {{0.f,0.f,0.f,0.f},{0.f,0.f,0.f,0.f}};

    const float* hbase = hs + (kq * 128) * 64 + bg * 4;
    const ulonglong2* ubase = (const ulonglong2*)Us2 + ((size_t)(kq * 128) * 4 + up) * 2;

    for (int s = 0; s < TSZ; ++s) {
        const int t   = dir ? (TSZ - 1 - s) : s;
        const int cur = s & 1, nxt = cur ^ 1;

        // stage h [512][64] into smem
        {
            const float4* src = (const float4*)&g_h[dir][cur][0];
            float4* dst = (float4*)hs;
#pragma unroll
            for (int i = 0; i < 32; ++i)
                dst[tid + i * 256] = src[tid + i * 256];
        }

        // acc init: kq0 folds xz (u64 load = exactly the unit-pair lanes)
        unsigned long long acc2[4][4];   // [batch][gate], lanes = (u0,u0+1)
        if (kq == 0) {
            const float* xzt = xz + ((size_t)t * 4) * BSZ * USZ;
#pragma unroll
            for (int g = 0; g < 4; ++g)
#pragma unroll
                for (int bi = 0; bi < 4; ++bi)
                    acc2[bi][g] = *(const unsigned long long*)
                        &xzt[((size_t)g * BSZ + bg * 4 + bi) * USZ + u0];
        } else {
#pragma unroll
            for (int g = 0; g < 4; ++g)
#pragma unroll
                for (int bi = 0; bi < 4; ++bi) acc2[bi][g] = 0ull;
        }
        __syncthreads();

        // inner loop: 128 k per thread
        {
            const float* hptr = hbase;
            const ulonglong2* uptr = ubase;
#pragma unroll 4
            for (int k = 0; k < 128; ++k) {
                float4 hv = *(const float4*)hptr; hptr += 64;
                ulonglong2 uv01 = uptr[0];
                ulonglong2 uv23 = uptr[1];
                uptr += 8;
                unsigned long long s0 = splat2(hv.x);
                unsigned long long s1 = splat2(hv.y);
                unsigned long long s2 = splat2(hv.z);
                unsigned long long s3 = splat2(hv.w);
                ffma2(acc2[0][0], s0, uv01.x); ffma2(acc2[0][1], s0, uv01.y);
                ffma2(acc2[0][2], s0, uv23.x); ffma2(acc2[0][3], s0, uv23.y);
                ffma2(acc2[1][0], s1, uv01.x); ffma2(acc2[1][1], s1, uv01.y);
                ffma2(acc2[1][2], s1, uv23.x); ffma2(acc2[1][3], s1, uv23.y);
                ffma2(acc2[2][0], s2, uv01.x); ffma2(acc2[2][1], s2, uv01.y);
                ffma2(acc2[2][2], s2, uv23.x); ffma2(acc2[2][3], s2, uv23.y);
                ffma2(acc2[3][0], s3, uv01.x); ffma2(acc2[3][1], s3, uv01.y);
                ffma2(acc2[3][2], s3, uv23.x); ffma2(acc2[3][3], s3, uv23.y);
            }
        }

        // reduction
        if (kq > 0) {
            unsigned long long* rp = red + ((size_t)(kq - 1) * 64 + r) * 16;
#pragma unroll
            for (int bi = 0; bi < 4; ++bi)
#pragma unroll
                for (int g = 0; g < 4; ++g) rp[bi * 4 + g] = acc2[bi][g];
        }
        __syncthreads();

        if (kq == 0) {
#pragma unroll
            for (int q = 0; q < 3; ++q) {
                const unsigned long long* rp = red + ((size_t)q * 64 + r) * 16;
#pragma unroll
                for (int bi = 0; bi < 4; ++bi)
#pragma unroll
                    for (int g = 0; g < 4; ++g) addf2(acc2[bi][g], rp[bi * 4 + g]);
            }

            const unsigned long long mw = msk[t];
#pragma unroll
            for (int bi = 0; bi < 4; ++bi) {
                int b = bg * 4 + bi;
                float zA[4], zB[4];
#pragma unroll
                for (int g = 0; g < 4; ++g) unpack2(acc2[bi][g], zA[g], zB[g]);
                bool m = (mw >> b) & 1ull;
                {
                    float ig = sigf(zA[0]), fg = sigf(zA[1]);
                    float gg = tanhf_(zA[2]), og = sigf(zA[3]);
                    float cn = fg * c_st[0][bi] + ig * gg;
                    float hn = og * tanhf_(cn);
                    if (m) { c_st[0][bi] = cn; h_st[0][bi] = hn; }
                }
                {
                    float ig = sigf(zB[0]), fg = sigf(zB[1]);
                    float gg = tanhf_(zB[2]), og = sigf(zB[3]);
                    float cn = fg * c_st[1][bi] + ig * gg;
                    float hn = og * tanhf_(cn);
                    if (m) { c_st[1][bi] = cn; h_st[1][bi] = hn; }
                }
                float2 hv = { h_st[0][bi], h_st[1][bi] };
                *(float2*)&out[((size_t)b * TSZ + t) * 1024 + dir * USZ + u0] = hv;
            }
            float4 h0 = { h_st[0][0], h_st[0][1], h_st[0][2], h_st[0][3] };
            float4 h1 = { h_st[1][0], h_st[1][1], h_st[1][2], h_st[1][3] };
            *(float4*)&g_h[dir][nxt][u0 * BSZ + bg * 4]       = h0;
            *(float4*)&g_h[dir][nxt][(u0 + 1) * BSZ + bg * 4] = h1;
        }
        grid_barrier(dir);
    }

    // final states
    if (kq == 0) {
        const size_t H0 = (size_t)BSZ * TSZ * 1024;
        const size_t C0 = H0 + (size_t)BSZ * 1024;
#pragma unroll
        for (int bi = 0; bi < 4; ++bi) {
            int b = bg * 4 + bi;
            float2 hv = { h_st[0][bi], h_st[1][bi] };
            float2 cv = { c_st[0][bi], c_st[1][bi] };
            *(float2*)&out[H0 + (size_t)b * 1024 + dir * USZ + u0] = hv;
            *(float2*)&out[C0 + (size_t)b * 1024 + dir * USZ + u0] = cv;
        }
    }
}

// ---------------------------------------------------------------------------
extern "C" void kernel_launch(void* const* d_in, const int* in_sizes, int n_in,
                              void* d_out, int out_size)
{
    const int*   idx = (const int*)  d_in[0];
    const float* emb = (const float*)d_in[1];
    const float* Wf  = (const float*)d_in[2];
    const float* Uf  = (const float*)d_in[3];
    const float* bf  = (const float*)d_in[4];
    const float* Wb  = (const float*)d_in[5];
    const float* Ub  = (const float*)d_in[6];
    const float* bb  = (const float*)d_in[7];
    float* out = (float*)d_out;

    dim3 ggrid(GSZ / 128, (BSZ * TSZ) / 128, 2);
    xz_gemm_kernel<<<ggrid, 256>>>(idx, emb, Wf, bf, Wb, bb);

    const int smem_bytes = 65536 + 131072 + 24576 + 4096;  // 225280
    cudaFuncSetAttribute(lstm_scan_kernel,
                         cudaFuncAttributeMaxDynamicSharedMemorySize, smem_bytes);
    lstm_scan_kernel<<<NBLK, 256, smem_bytes>>>(idx, Uf, Ub, out);
}